// round 17
// baseline (speedup 1.0000x reference)
#include <cuda_runtime.h>
#include <cstdint>

#define T_DIM 256
#define C_DIM 128
#define L_DIM 48
#define STAGES 7            // ring stages (8 rows x 512B = 4KB each, 28KB)
#define BLK    8            // rows (time steps) per stage
#define NBLK   (T_DIM / BLK)   // 32 blocks
#define STAGE_BYTES (BLK * C_DIM * 4)

__device__ __forceinline__ void mbar_wait(uint32_t mb, uint32_t par) {
    uint32_t done;
    asm volatile(
        "{\n\t.reg .pred p;\n\t"
        "mbarrier.try_wait.parity.acquire.cta.shared::cta.b64 p, [%1], %2;\n\t"
        "selp.b32 %0, 1, 0, p;\n\t}"
        : "=r"(done) : "r"(mb), "r"(par) : "memory");
    if (!done) {
        asm volatile(
            "{\n\t.reg .pred P1;\n\t"
            "W_%=:\n\t"
            "mbarrier.try_wait.parity.acquire.cta.shared::cta.b64 P1, [%0], %1, 0x989680;\n\t"
            "@P1 bra.uni D_%=;\n\t"
            "bra.uni W_%=;\n\t"
            "D_%=:\n\t}"
            :: "r"(mb), "r"(par) : "memory");
    }
}

__device__ __forceinline__ void tma_issue(uint32_t dst, const float* src, uint32_t mb) {
    asm volatile("fence.proxy.async.shared::cta;" ::: "memory");
    asm volatile("mbarrier.arrive.expect_tx.shared.b64 _, [%0], %1;"
                 :: "r"(mb), "r"(STAGE_BYTES) : "memory");
    asm volatile(
        "cp.async.bulk.shared::cluster.global.mbarrier::complete_tx::bytes "
        "[%0], [%1], %2, [%3];"
        :: "r"(dst), "l"(src), "r"(STAGE_BYTES), "r"(mb) : "memory");
}

// One warp per batch element. lane holds extended states s = 4*lane + j, j=0..3.
// S = 2*48+1 = 97: lanes 0..23 fully valid, lane 24 only j=0 (s=96).
// Linear-space CTC forward, 128x prescale, exact power-of-2 renorm per 8 steps.
// Rows stream GMEM->SMEM via cp.async.bulk (TMA) + mbarrier; 7 stages (28KB)
// outstanding per warp, next stage issued at block TOP to shorten round-trip.
__global__ __launch_bounds__(32)
void ctc_fwd_kernel(const float* __restrict__ y,      // [B, T, C] softmax probs
                    const int*   __restrict__ labels, // [B, L]
                    float*       __restrict__ out)    // [B]
{
    __shared__ alignas(1024) float ring[STAGES][BLK][C_DIM];  // 28 KB
    __shared__ alignas(8) uint64_t mbar[STAGES];

    const int b    = blockIdx.x;
    const int lane = threadIdx.x;

    const float* yb = y + (size_t)b * (T_DIM * C_DIM);
    const int*   lb = labels + (size_t)b * L_DIM;

    const uint32_t ring_s = (uint32_t)__cvta_generic_to_shared(&ring[0][0][0]);
    const uint32_t mbar_s = (uint32_t)__cvta_generic_to_shared(&mbar[0]);

    if (lane == 0) {
#pragma unroll
        for (int s = 0; s < STAGES; s++)
            asm volatile("mbarrier.init.shared.b64 [%0], %1;"
                         :: "r"(mbar_s + s * 8), "r"(1) : "memory");
    }
    __syncwarp();

    // --- prologue: issue stages 0..5 ---
    if (lane == 0) {
#pragma unroll
        for (int k = 0; k < STAGES - 1; k++)
            tma_issue(ring_s + k * STAGE_BYTES, yb + (size_t)k * BLK * C_DIM,
                      mbar_s + k * 8);
    }

    // --- per-lane static state ---
    const bool lv = (lane < 24);
    int c0 = 127, c1 = 127, cm1 = -1;
    if (lv) { c0 = lb[2 * lane]; c1 = lb[2 * lane + 1]; }
    if (lane >= 1 && lane < 24) cm1 = lb[2 * lane - 1];

    const float m1 = (lane >= 1 && lv && c0 != cm1) ? 1.0f : 0.0f; // skip into s=4l+1
    const float m3 = (lv && c1 != c0)               ? 1.0f : 0.0f; // skip into s=4l+3
    const bool  v0  = (lane <= 24);
    const bool  v13 = lv;

    const float SC = 128.0f, EB = 1.28e-5f;   // p_scaled = fmaf(p, 128, 128e-7)

    float a0 = 0.0f, a1 = 0.0f, a2 = 0.0f, a3 = 0.0f;
    int acc_e = 0;                            // accumulated base-2 exponent

    for (int k = 0; k < NBLK; k++) {
        const int st = k % STAGES;
        const uint32_t par = (uint32_t)((k / STAGES) & 1);

        // issue stage k+STAGES-1 at TOP (its slot was consumed at block k-1;
        // the end-of-block syncwarp ordered all lanes' reads before this)
        const int kn = k + STAGES - 1;
        if (lane == 0 && kn < NBLK) {
            const int sn = kn % STAGES;
            tma_issue(ring_s + sn * STAGE_BYTES, yb + (size_t)kn * BLK * C_DIM,
                      mbar_s + sn * 8);
        }

        mbar_wait(mbar_s + st * 8, par);

        const float* rows = &ring[st][0][0];
        int d0 = 0;
        if (k == 0) {
            // t = 0 init: alpha[0] = p(blank), alpha[1] = p(label0)
            const float pb = rows[127];
            const float p0 = rows[c0];
            a0 = (lane == 0) ? fmaf(pb, SC, EB) : 0.0f;
            a1 = (lane == 0) ? fmaf(p0, SC, EB) : 0.0f;
            d0 = 1;
        }
#pragma unroll
        for (int d = 0; d < BLK; d++) {
            if (d < d0) continue;
            const float* row = rows + d * C_DIM;
            const float pb = row[127];
            const float g0 = row[c0];
            const float g1 = row[c1];

            const float pcb  = v0  ? fmaf(pb, SC, EB) : 0.0f;  // blank, s=4l
            const float pcb2 = v13 ? fmaf(pb, SC, EB) : 0.0f;  // blank, s=4l+2
            const float pc1  = v13 ? fmaf(g0, SC, EB) : 0.0f;
            const float pc3  = v13 ? fmaf(g1, SC, EB) : 0.0f;

            float up3 = __shfl_up_sync(0xffffffffu, a3, 1);    // alpha[4l-1]
            if (lane == 0) up3 = 0.0f;
            const float n0 = (a0 + up3)             * pcb;     // s=4l
            const float n1 = fmaf(m1, up3, a1 + a0) * pc1;     // s=4l+1
            const float n2 = (a2 + a1)              * pcb2;    // s=4l+2
            const float n3 = fmaf(m3, a1, a3 + a2)  * pc3;     // s=4l+3
            a0 = n0; a1 = n1; a2 = n2; a3 = n3;
        }

        // exact power-of-2 renorm (commutes through the linear recurrence)
        float sum = (a0 + a1) + (a2 + a3);
#pragma unroll
        for (int o = 16; o; o >>= 1) sum += __shfl_xor_sync(0xffffffffu, sum, o);
        const int e = (__float_as_int(sum) >> 23) & 0xff;      // biased exponent
        const float inv = __int_as_float((254 - e) << 23);      // 2^(127-e)
        acc_e += e - 127;
        a0 *= inv; a1 *= inv; a2 *= inv; a3 *= inv;

        __syncwarp();   // all lanes done reading stage st before its reuse
    }

    // loss = T*log(128) - acc_e*ln2 - log(alpha[95] + alpha[96])
    const float v95 = __shfl_sync(0xffffffffu, a3, 23);  // s = 95
    const float v96 = __shfl_sync(0xffffffffu, a0, 24);  // s = 96
    if (lane == 0) {
        const float offs = 1242.11974756972f;            // 256 * ln(128)
        out[b] = offs - (float)acc_e * 0.69314718056f - __logf(v95 + v96);
    }
}

extern "C" void kernel_launch(void* const* d_in, const int* in_sizes, int n_in,
                              void* d_out, int out_size)
{
    const float* y      = (const float*)d_in[0];   // [B, T, C] float32
    const int*   labels = (const int*)d_in[1];     // [B, L] int32
    float*       out    = (float*)d_out;           // [B, 1] float32
    const int B = in_sizes[1] / L_DIM;
    ctc_fwd_kernel<<<B, 32>>>(y, labels, out);
}